// round 2
// baseline (speedup 1.0000x reference)
#include <cuda_runtime.h>

// Problem constants
#define B_ 2
#define T_ 320
#define L_ 207
#define D_ 64
#define S_ 21
#define SL_ (S_ * L_)   // 4347

// Scratch: sim/soft buffer [B, S*L, L] = 7.2 MB (static device global, no alloc)
__device__ float g_sim[(size_t)B_ * S_ * L_ * L_];

__device__ __forceinline__ int shift_p(int s) { return (s == 0) ? 287 : (21 - s); }

// ---------------------------------------------------------------------------
// Kernel 1: g_sim[b,s,l,m] = (w/T) * sum_{t,d} x[b,t,l,d] * x[b,t+p,m,d]
// 64x64 tile per block, 16x16 threads, 4x4 microtile, K-chunk = 16.
// ---------------------------------------------------------------------------
__global__ __launch_bounds__(256) void sim_gemm(const float* __restrict__ x,
                                                const float* __restrict__ w) {
    const int bs = blockIdx.z;
    const int b = bs / S_;
    const int s = bs % S_;
    const int p = shift_p(s);
    const int Tv = T_ - p;                 // valid time steps
    const int l0 = blockIdx.x * 64;
    const int m0 = blockIdx.y * 64;

    __shared__ float As[64][17];
    __shared__ float Bs[64][17];

    const int tx = threadIdx.x, ty = threadIdx.y;
    const int tid = ty * 16 + tx;
    const int lr = tid >> 2;               // 0..63: row within tile (load)
    const int kc4 = (tid & 3) << 2;        // 0,4,8,12: k offset (load)

    float acc[4][4] = {};

    const float* xb = x + (size_t)b * T_ * L_ * D_;
    const int la = l0 + lr;
    const int ma = m0 + lr;
    const bool lv = la < L_;
    const bool mv = ma < L_;

    const int nk = Tv * 4;                 // K = Tv*64, chunks of 16
    for (int kc = 0; kc < nk; ++kc) {
        const int t = kc >> 2;
        const int db = ((kc & 3) << 4) + kc4;   // d offset within [0,64)
        float4 va = make_float4(0.f, 0.f, 0.f, 0.f);
        float4 vb = make_float4(0.f, 0.f, 0.f, 0.f);
        if (lv) va = *(const float4*)(xb + ((size_t)t * L_ + la) * D_ + db);
        if (mv) vb = *(const float4*)(xb + ((size_t)(t + p) * L_ + ma) * D_ + db);
        As[lr][kc4 + 0] = va.x; As[lr][kc4 + 1] = va.y;
        As[lr][kc4 + 2] = va.z; As[lr][kc4 + 3] = va.w;
        Bs[lr][kc4 + 0] = vb.x; Bs[lr][kc4 + 1] = vb.y;
        Bs[lr][kc4 + 2] = vb.z; Bs[lr][kc4 + 3] = vb.w;
        __syncthreads();
#pragma unroll
        for (int kk = 0; kk < 16; ++kk) {
            float a[4], bv[4];
#pragma unroll
            for (int i = 0; i < 4; ++i) a[i] = As[ty + 16 * i][kk];
#pragma unroll
            for (int j = 0; j < 4; ++j) bv[j] = Bs[tx + 16 * j][kk];
#pragma unroll
            for (int i = 0; i < 4; ++i)
#pragma unroll
                for (int j = 0; j < 4; ++j)
                    acc[i][j] = fmaf(a[i], bv[j], acc[i][j]);
        }
        __syncthreads();
    }

    const float sc = w[0] * (1.f / (float)T_);
    float* C = g_sim + (size_t)(b * S_ + s) * L_ * L_;
#pragma unroll
    for (int i = 0; i < 4; ++i) {
        const int l = l0 + ty + 16 * i;
        if (l >= L_) continue;
#pragma unroll
        for (int j = 0; j < 4; ++j) {
            const int m = m0 + tx + 16 * j;
            if (m < L_) C[(size_t)l * L_ + m] = acc[i][j] * sc;
        }
    }
}

// ---------------------------------------------------------------------------
// Kernel 2: in-place softmax over j = s*L+l (4347 values, stride L) per (b,m).
// ---------------------------------------------------------------------------
__global__ __launch_bounds__(256) void softmax_cols() {
    const int bm = blockIdx.x;
    const int b = bm / L_;
    const int m = bm % L_;
    float* base = g_sim + (size_t)b * S_ * L_ * L_ + m;

    __shared__ float red[256];
    const int tid = threadIdx.x;

    float mx = -1e30f;
    for (int j = tid; j < SL_; j += 256) mx = fmaxf(mx, base[(size_t)j * L_]);
    red[tid] = mx;
    __syncthreads();
    for (int o = 128; o > 0; o >>= 1) {
        if (tid < o) red[tid] = fmaxf(red[tid], red[tid + o]);
        __syncthreads();
    }
    mx = red[0];
    __syncthreads();

    float sum = 0.f;
    for (int j = tid; j < SL_; j += 256) {
        float e = __expf(base[(size_t)j * L_] - mx);
        base[(size_t)j * L_] = e;
        sum += e;
    }
    red[tid] = sum;
    __syncthreads();
    for (int o = 128; o > 0; o >>= 1) {
        if (tid < o) red[tid] += red[tid + o];
        __syncthreads();
    }
    const float inv = 1.f / red[0];
    for (int j = tid; j < SL_; j += 256) base[(size_t)j * L_] *= inv;
}

// ---------------------------------------------------------------------------
// Kernel 3: out[b,t,l,d] = sum_j attn[b,l,j] * XF[b,t,j,d]
//   attn[b,l,j] = g_sim linear buffer (reshape is a view)
//   XF[b,t,j,d] = x[b, t+p_{j/L}, j%L, d] (zero when t+p >= T)
// Tile: 64 l x 64 d per block, K chunks of 16 over j.
// ---------------------------------------------------------------------------
__global__ __launch_bounds__(256) void out_gemm(const float* __restrict__ x,
                                                float* __restrict__ out) {
    const int bt = blockIdx.z;
    const int b = bt / T_;
    const int t = bt % T_;
    const int l0 = blockIdx.x * 64;

    __shared__ float As[64][17];   // attn tile: 64 l x 16 j
    __shared__ float Bs[16][68];   // XF tile:  16 j x 64 d

    const int tx = threadIdx.x, ty = threadIdx.y;
    const int tid = ty * 16 + tx;
    const int lr = tid >> 2;
    const int kc4 = (tid & 3) << 2;
    const int br = tid >> 4;           // 0..15 (j row)
    const int bc = (tid & 15) << 2;    // 0..60 (d col)

    float acc[4][4] = {};

    const float* attnb = g_sim + (size_t)b * S_ * L_ * L_;
    const float* xb = x + (size_t)b * T_ * L_ * D_;
    const int la = l0 + lr;
    const bool lv = la < L_;

    const int nk = (SL_ + 15) >> 4;    // 272
    for (int kc = 0; kc < nk; ++kc) {
        const int j0 = kc << 4;
        // attn tile (SL_ = 4347 is odd -> scalar loads, no float4 alignment)
        {
            const float* arow = attnb + (size_t)la * SL_ + j0 + kc4;
#pragma unroll
            for (int c = 0; c < 4; ++c) {
                const int j = j0 + kc4 + c;
                As[lr][kc4 + c] = (lv && j < SL_) ? arow[c] : 0.f;
            }
        }
        // XF tile
        {
            const int j = j0 + br;
            float4 v = make_float4(0.f, 0.f, 0.f, 0.f);
            if (j < SL_) {
                const int s = j / L_;
                const int link = j - s * L_;
                const int tp = t + shift_p(s);
                if (tp < T_)
                    v = *(const float4*)(xb + ((size_t)tp * L_ + link) * D_ + bc);
            }
            *(float4*)&Bs[br][bc] = v;
        }
        __syncthreads();
#pragma unroll
        for (int kk = 0; kk < 16; ++kk) {
            float a[4], bv[4];
#pragma unroll
            for (int i = 0; i < 4; ++i) a[i] = As[ty + 16 * i][kk];
#pragma unroll
            for (int j = 0; j < 4; ++j) bv[j] = Bs[kk][tx + 16 * j];
#pragma unroll
            for (int i = 0; i < 4; ++i)
#pragma unroll
                for (int j = 0; j < 4; ++j)
                    acc[i][j] = fmaf(a[i], bv[j], acc[i][j]);
        }
        __syncthreads();
    }

    float* ob = out + (size_t)(b * T_ + t) * L_ * D_;
#pragma unroll
    for (int i = 0; i < 4; ++i) {
        const int l = l0 + ty + 16 * i;
        if (l >= L_) continue;
#pragma unroll
        for (int j = 0; j < 4; ++j) {
            const int d = tx + 16 * j;
            ob[(size_t)l * D_ + d] = acc[i][j];
        }
    }
}

// ---------------------------------------------------------------------------
extern "C" void kernel_launch(void* const* d_in, const int* in_sizes, int n_in,
                              void* d_out, int out_size) {
    const float* x = (const float*)d_in[0];
    const float* w = (const float*)d_in[1];
    float* out = (float*)d_out;

    dim3 blk(16, 16);
    sim_gemm<<<dim3(4, 4, B_ * S_), blk>>>(x, w);
    softmax_cols<<<B_ * L_, 256>>>();
    out_gemm<<<dim3(4, 1, B_ * T_), blk>>>(x, out);
}

// round 3
// speedup vs baseline: 1.2913x; 1.2913x over previous
#include <cuda_runtime.h>

// Problem constants
#define B_ 2
#define T_ 320
#define L_ 207
#define D_ 64
#define S_ 21
#define SL_ (S_ * L_)   // 4347
#define KC 16           // K-chunk per smem tile

// Scratch: sim/soft buffer [B, S*L, L] = 7.2 MB (static device global, no alloc)
__device__ float g_sim[(size_t)B_ * S_ * L_ * L_];

__device__ __forceinline__ int shift_p(int s) { return (s == 0) ? 287 : (21 - s); }

// ---- packed f32x2 helpers (Blackwell FFMA2 path) ----
#define PACKF2(d, lo, hi) \
    asm("mov.b64 %0, {%1, %2};" : "=l"(d) : "r"(__float_as_uint(lo)), "r"(__float_as_uint(hi)))
#define FMA2(d, a, b) \
    asm("fma.rn.f32x2 %0, %1, %2, %0;" : "+l"(d) : "l"(a), "l"(b))
#define UNPACKF2(lo, hi, v) do { unsigned int _ul, _uh;                           \
    asm("mov.b64 {%0, %1}, %2;" : "=r"(_ul), "=r"(_uh) : "l"(v));                 \
    (lo) = __uint_as_float(_ul); (hi) = __uint_as_float(_uh); } while (0)

// ---------------------------------------------------------------------------
// Kernel 1: g_sim[b,s,l,m] = (w/T) * sum_{t,d} x[b,t,l,d] * x[b,t+p,m,d]
// 64x64 tile, 256 threads, 4x4 microtile via f32x2 pairs, k-major smem,
// register-staged double buffering.
// ---------------------------------------------------------------------------
__global__ __launch_bounds__(256) void sim_gemm(const float* __restrict__ x,
                                                const float* __restrict__ w) {
    const int bs = blockIdx.z;
    const int b = bs / S_;
    const int s = bs % S_;
    const int p = shift_p(s);
    const int Tv = T_ - p;
    const int l0 = blockIdx.x * 64;
    const int m0 = blockIdx.y * 64;

    __shared__ float As[2][KC][68];   // k-major: As[k][l], stride 68 (16B aligned rows)
    __shared__ float Bs[2][KC][68];

    const int tid = threadIdx.x;
    const int lr  = tid >> 2;          // 0..63 load row
    const int kc4 = (tid & 3) << 2;    // 0,4,8,12 load k-offset
    const int tx  = tid & 15;          // compute col group
    const int ty  = tid >> 4;          // compute row group

    const float* xb = x + (size_t)b * T_ * L_ * D_;
    const int la = l0 + lr;
    const int ma = m0 + lr;
    const bool lv = la < L_;
    const bool mv = ma < L_;

    const int nc = Tv * 4;             // chunks of 16 k (k = t*64+d)

    float4 ra, rb;                     // register staging for next chunk
#define SIM_LDG(KCH) do {                                                         \
        const int _t  = (KCH) >> 2;                                               \
        const int _db = (((KCH) & 3) << 4) + kc4;                                 \
        ra = make_float4(0.f, 0.f, 0.f, 0.f);                                     \
        rb = make_float4(0.f, 0.f, 0.f, 0.f);                                     \
        if (lv) ra = *(const float4*)(xb + ((size_t)_t * L_ + la) * D_ + _db);    \
        if (mv) rb = *(const float4*)(xb + ((size_t)(_t + p) * L_ + ma) * D_ + _db); \
    } while (0)
#define SIM_STS(BUF) do {                                                         \
        As[BUF][kc4 + 0][lr] = ra.x; As[BUF][kc4 + 1][lr] = ra.y;                 \
        As[BUF][kc4 + 2][lr] = ra.z; As[BUF][kc4 + 3][lr] = ra.w;                 \
        Bs[BUF][kc4 + 0][lr] = rb.x; Bs[BUF][kc4 + 1][lr] = rb.y;                 \
        Bs[BUF][kc4 + 2][lr] = rb.z; Bs[BUF][kc4 + 3][lr] = rb.w;                 \
    } while (0)

    unsigned long long acc[2][4] = {};   // (lpair 0: l+0/l+1, lpair 1: l+2/l+3) x 4 m

    SIM_LDG(0); SIM_STS(0); SIM_LDG(1);
    __syncthreads();

    for (int kc = 0; kc < nc; ++kc) {
        const int cur = kc & 1;
        if (kc + 1 < nc) SIM_STS(cur ^ 1);
        if (kc + 2 < nc) SIM_LDG(kc + 2);
#pragma unroll
        for (int k = 0; k < KC; ++k) {
            const float4 a4 = *(const float4*)&As[cur][k][ty << 2];
            const float4 b4 = *(const float4*)&Bs[cur][k][tx << 2];
            unsigned long long a01, a23, bb;
            PACKF2(a01, a4.x, a4.y);
            PACKF2(a23, a4.z, a4.w);
            PACKF2(bb, b4.x, b4.x); FMA2(acc[0][0], a01, bb); FMA2(acc[1][0], a23, bb);
            PACKF2(bb, b4.y, b4.y); FMA2(acc[0][1], a01, bb); FMA2(acc[1][1], a23, bb);
            PACKF2(bb, b4.z, b4.z); FMA2(acc[0][2], a01, bb); FMA2(acc[1][2], a23, bb);
            PACKF2(bb, b4.w, b4.w); FMA2(acc[0][3], a01, bb); FMA2(acc[1][3], a23, bb);
        }
        __syncthreads();
    }

    const float sc = w[0] * (1.f / (float)T_);
    float* C = g_sim + (size_t)(b * S_ + s) * L_ * L_;
#pragma unroll
    for (int ip = 0; ip < 2; ++ip) {
#pragma unroll
        for (int j = 0; j < 4; ++j) {
            float vlo, vhi;
            UNPACKF2(vlo, vhi, acc[ip][j]);
            const int l = l0 + (ty << 2) + (ip << 1);
            const int m = m0 + (tx << 2) + j;
            if (m < L_) {
                if (l < L_)     C[(size_t)l * L_ + m]       = vlo * sc;
                if (l + 1 < L_) C[(size_t)(l + 1) * L_ + m] = vhi * sc;
            }
        }
    }
#undef SIM_LDG
#undef SIM_STS
}

// ---------------------------------------------------------------------------
// Kernel 2: in-place softmax over j = s*L+l (4347 values, stride L) per (b,m).
// ---------------------------------------------------------------------------
__global__ __launch_bounds__(256) void softmax_cols() {
    const int bm = blockIdx.x;
    const int b = bm / L_;
    const int m = bm % L_;
    float* base = g_sim + (size_t)b * S_ * L_ * L_ + m;

    __shared__ float red[256];
    const int tid = threadIdx.x;

    float mx = -1e30f;
    for (int j = tid; j < SL_; j += 256) mx = fmaxf(mx, base[(size_t)j * L_]);
    red[tid] = mx;
    __syncthreads();
    for (int o = 128; o > 0; o >>= 1) {
        if (tid < o) red[tid] = fmaxf(red[tid], red[tid + o]);
        __syncthreads();
    }
    mx = red[0];
    __syncthreads();

    float sum = 0.f;
    for (int j = tid; j < SL_; j += 256) {
        float e = __expf(base[(size_t)j * L_] - mx);
        base[(size_t)j * L_] = e;
        sum += e;
    }
    red[tid] = sum;
    __syncthreads();
    for (int o = 128; o > 0; o >>= 1) {
        if (tid < o) red[tid] += red[tid + o];
        __syncthreads();
    }
    const float inv = 1.f / red[0];
    for (int j = tid; j < SL_; j += 256) base[(size_t)j * L_] *= inv;
}

// ---------------------------------------------------------------------------
// Kernel 3: out[b,t,l,d] = sum_j attn[b,l,j] * XF[b,t,j,d]
//   attn[b,l,j] = g_sim linear buffer (reshape is a view)
//   XF[b,t,j,d] = x[b, t+p_{j/L}, j%L, d] (zero when t+p >= T)
// Same f32x2 double-buffered core. K = SL_ (4347) over j.
// ---------------------------------------------------------------------------
__global__ __launch_bounds__(256) void out_gemm(const float* __restrict__ x,
                                                float* __restrict__ out) {
    const int bt = blockIdx.z;
    const int b = bt / T_;
    const int t = bt % T_;
    const int l0 = blockIdx.x * 64;

    __shared__ float As[2][KC][68];   // k-major attn tile: As[j][l]
    __shared__ float Bs[2][KC][68];   // XF tile: Bs[j][d] (natural row-major)

    const int tid = threadIdx.x;
    const int lr  = tid >> 2;
    const int kc4 = (tid & 3) << 2;
    const int br  = tid >> 4;          // 0..15 j row (B loader)
    const int bc  = (tid & 15) << 2;   // 0..60 d col (B loader)
    const int tx  = tid & 15;
    const int ty  = tid >> 4;

    const float* attnb = g_sim + (size_t)b * S_ * L_ * L_;
    const float* xb    = x + (size_t)b * T_ * L_ * D_;
    const int la = l0 + lr;
    const bool lv = la < L_;

    const int nc = (SL_ + KC - 1) / KC;   // 272 (last partial)

    float raA[4];
    float4 rb;
#define OUT_LDG(KCH) do {                                                         \
        const int _j0 = (KCH) << 4;                                               \
        const float* _ar = attnb + (size_t)la * SL_ + _j0 + kc4;                  \
        _Pragma("unroll")                                                         \
        for (int _c = 0; _c < 4; ++_c) {                                          \
            const int _j = _j0 + kc4 + _c;                                        \
            raA[_c] = (lv && _j < SL_) ? _ar[_c] : 0.f;                           \
        }                                                                         \
        rb = make_float4(0.f, 0.f, 0.f, 0.f);                                     \
        const int _jb = _j0 + br;                                                 \
        if (_jb < SL_) {                                                          \
            const int _s = _jb / L_;                                              \
            const int _lk = _jb - _s * L_;                                        \
            const int _tp = t + shift_p(_s);                                      \
            if (_tp < T_)                                                         \
                rb = *(const float4*)(xb + ((size_t)_tp * L_ + _lk) * D_ + bc);   \
        }                                                                         \
    } while (0)
#define OUT_STS(BUF) do {                                                         \
        As[BUF][kc4 + 0][lr] = raA[0]; As[BUF][kc4 + 1][lr] = raA[1];             \
        As[BUF][kc4 + 2][lr] = raA[2]; As[BUF][kc4 + 3][lr] = raA[3];             \
        *(float4*)&Bs[BUF][br][bc] = rb;                                          \
    } while (0)

    unsigned long long acc[2][4] = {};

    OUT_LDG(0); OUT_STS(0); OUT_LDG(1);
    __syncthreads();

    for (int kc = 0; kc < nc; ++kc) {
        const int cur = kc & 1;
        if (kc + 1 < nc) OUT_STS(cur ^ 1);
        if (kc + 2 < nc) OUT_LDG(kc + 2);
#pragma unroll
        for (int k = 0; k < KC; ++k) {
            const float4 a4 = *(const float4*)&As[cur][k][ty << 2];
            const float4 b4 = *(const float4*)&Bs[cur][k][tx << 2];
            unsigned long long a01, a23, bb;
            PACKF2(a01, a4.x, a4.y);
            PACKF2(a23, a4.z, a4.w);
            PACKF2(bb, b4.x, b4.x); FMA2(acc[0][0], a01, bb); FMA2(acc[1][0], a23, bb);
            PACKF2(bb, b4.y, b4.y); FMA2(acc[0][1], a01, bb); FMA2(acc[1][1], a23, bb);
            PACKF2(bb, b4.z, b4.z); FMA2(acc[0][2], a01, bb); FMA2(acc[1][2], a23, bb);
            PACKF2(bb, b4.w, b4.w); FMA2(acc[0][3], a01, bb); FMA2(acc[1][3], a23, bb);
        }
        __syncthreads();
    }

    float* ob = out + (size_t)(b * T_ + t) * L_ * D_;
#pragma unroll
    for (int ip = 0; ip < 2; ++ip) {
#pragma unroll
        for (int j = 0; j < 4; ++j) {
            float vlo, vhi;
            UNPACKF2(vlo, vhi, acc[ip][j]);
            const int l = l0 + (ty << 2) + (ip << 1);
            const int d = (tx << 2) + j;
            if (l < L_)     ob[(size_t)l * D_ + d]       = vlo;
            if (l + 1 < L_) ob[(size_t)(l + 1) * D_ + d] = vhi;
        }
    }
#undef OUT_LDG
#undef OUT_STS
}

// ---------------------------------------------------------------------------
extern "C" void kernel_launch(void* const* d_in, const int* in_sizes, int n_in,
                              void* d_out, int out_size) {
    const float* x = (const float*)d_in[0];
    const float* w = (const float*)d_in[1];
    float* out = (float*)d_out;

    sim_gemm<<<dim3(4, 4, B_ * S_), 256>>>(x, w);
    softmax_cols<<<B_ * L_, 256>>>();
    out_gemm<<<dim3(4, 1, B_ * T_), 256>>>(x, out);
}

// round 4
// speedup vs baseline: 2.4242x; 1.8774x over previous
#include <cuda_runtime.h>
#include <cuda_bf16.h>

// Problem constants
#define B_ 2
#define T_ 320
#define L_ 207
#define D_ 64
#define S_ 21
#define SL_ 4347
#define SLP_ 4352       // padded attn row stride (float4-aligned)

// Scratch (static device globals; no allocation)
__device__ float g_sim[(size_t)B_ * SL_ * L_];       // [b][s*L+l][m]
__device__ float g_attn[(size_t)B_ * L_ * SLP_];     // [b][l][j] padded

__device__ __forceinline__ int shift_p(int s) { return (s == 0) ? 287 : (21 - s); }

// ---------------- low-level helpers ----------------
__device__ __forceinline__ unsigned sptr(const void* p) {
    unsigned r;
    asm("{.reg .u64 t; cvta.to.shared.u64 t, %1; cvt.u32.u64 %0, t;}" : "=r"(r) : "l"(p));
    return r;
}
__device__ __forceinline__ void ldsm4(unsigned r[4], unsigned a) {
    asm volatile("ldmatrix.sync.aligned.m8n8.x4.shared.b16 {%0,%1,%2,%3},[%4];"
                 : "=r"(r[0]), "=r"(r[1]), "=r"(r[2]), "=r"(r[3]) : "r"(a));
}
__device__ __forceinline__ void ldsm4t(unsigned r[4], unsigned a) {
    asm volatile("ldmatrix.sync.aligned.m8n8.x4.trans.shared.b16 {%0,%1,%2,%3},[%4];"
                 : "=r"(r[0]), "=r"(r[1]), "=r"(r[2]), "=r"(r[3]) : "r"(a));
}
__device__ __forceinline__ void mma16816(float c[4], const unsigned a[4],
                                         unsigned b0, unsigned b1) {
    asm volatile("mma.sync.aligned.m16n8k16.row.col.f32.bf16.bf16.f32 "
                 "{%0,%1,%2,%3},{%4,%5,%6,%7},{%8,%9},{%0,%1,%2,%3};"
                 : "+f"(c[0]), "+f"(c[1]), "+f"(c[2]), "+f"(c[3])
                 : "r"(a[0]), "r"(a[1]), "r"(a[2]), "r"(a[3]), "r"(b0), "r"(b1));
}
// fp32x4 -> hi/lo bf16x4 into smem (8 bytes each)
__device__ __forceinline__ void cvt_hl(char* hp, char* lp, float4 v) {
    __nv_bfloat16 h0 = __float2bfloat16(v.x), h1 = __float2bfloat16(v.y);
    __nv_bfloat16 h2 = __float2bfloat16(v.z), h3 = __float2bfloat16(v.w);
    *(__nv_bfloat162*)(hp)     = __halves2bfloat162(h0, h1);
    *(__nv_bfloat162*)(hp + 4) = __halves2bfloat162(h2, h3);
    __nv_bfloat16 q0 = __float2bfloat16(v.x - __bfloat162float(h0));
    __nv_bfloat16 q1 = __float2bfloat16(v.y - __bfloat162float(h1));
    __nv_bfloat16 q2 = __float2bfloat16(v.z - __bfloat162float(h2));
    __nv_bfloat16 q3 = __float2bfloat16(v.w - __bfloat162float(h3));
    *(__nv_bfloat162*)(lp)     = __halves2bfloat162(q0, q1);
    *(__nv_bfloat162*)(lp + 4) = __halves2bfloat162(q2, q3);
}

// ---------------------------------------------------------------------------
// Kernel 1: sim GEMM. C[l,m] = (w/T) * sum_k x[t,l,:].x[t+p,m,:]
// Block tile 128x128, KC=32, 8 warps (warp tile 64x32), bf16 split 3-pass MMA.
// smem per stage: Ah,Al,Bh,Bl each 128 rows * 80B (32 bf16 + pad).
// ---------------------------------------------------------------------------
#define SIM_TILEB 10240
#define SIM_STAGE (4 * SIM_TILEB)
#define SIM_SMEM  (2 * SIM_STAGE)

__global__ __launch_bounds__(256, 1) void sim_gemm(const float* __restrict__ x,
                                                   const float* __restrict__ w) {
    extern __shared__ char sm[];
    const int z = blockIdx.z;
    const int b = z & 1;
    const int s = ((z >> 1) + 1) % S_;      // s=0 (tiny K) scheduled last
    const int p = shift_p(s);
    const int Tv = T_ - p;
    const int l0 = blockIdx.x * 128, m0 = blockIdx.y * 128;
    const int tid = threadIdx.x, lane = tid & 31, wid = tid >> 5;
    const int wl = (wid & 1) * 64, wm = (wid >> 1) * 32;
    const float* xb = x + (size_t)b * T_ * L_ * D_;

    // ldmatrix lane addressing
    const int rA = lane & 15, cA = lane >> 4;                    // A: row, k-half
    const int nB = ((lane >> 4) << 3) + (lane & 7);              // B: n row
    const int kB = ((lane >> 3) & 1) << 3;                       // B: k-half

    int rowi[4], c4i[4];
#pragma unroll
    for (int i = 0; i < 4; i++) { int e = tid + i * 256; rowi[i] = e >> 3; c4i[i] = e & 7; }

    float4 stA[4], stB[4];
    auto LDG = [&](int kc) {
        const int t = kc >> 1, db = (kc & 1) * 32;
#pragma unroll
        for (int i = 0; i < 4; i++) {
            const int row = rowi[i], k4 = c4i[i] * 4;
            stA[i] = make_float4(0.f, 0.f, 0.f, 0.f);
            stB[i] = make_float4(0.f, 0.f, 0.f, 0.f);
            if (l0 + row < L_)
                stA[i] = *(const float4*)(xb + ((size_t)t * L_ + l0 + row) * D_ + db + k4);
            if (m0 + row < L_)
                stB[i] = *(const float4*)(xb + ((size_t)(t + p) * L_ + m0 + row) * D_ + db + k4);
        }
    };
    auto STS = [&](int buf) {
        char* base = sm + buf * SIM_STAGE;
#pragma unroll
        for (int i = 0; i < 4; i++) {
            const int off = rowi[i] * 80 + c4i[i] * 8;
            cvt_hl(base + off, base + SIM_TILEB + off, stA[i]);
            cvt_hl(base + 2 * SIM_TILEB + off, base + 3 * SIM_TILEB + off, stB[i]);
        }
    };

    float acc[4][4][4] = {};
    const int nc = Tv * 2;

    LDG(0); STS(0); LDG(1);
    __syncthreads();

    for (int kc = 0; kc < nc; ++kc) {
        const int cur = kc & 1;
        if (kc + 1 < nc) STS(cur ^ 1);
        if (kc + 2 < nc) LDG(kc + 2);
        const unsigned base = sptr(sm + cur * SIM_STAGE);
#pragma unroll
        for (int s16 = 0; s16 < 2; ++s16) {
            unsigned ah[4][4], al[4][4], bh[2][4], bl[2][4];
#pragma unroll
            for (int mt = 0; mt < 4; ++mt) {
                const unsigned o = base + (wl + mt * 16 + rA) * 80 + (s16 * 16 + cA * 8) * 2;
                ldsm4(ah[mt], o);
                ldsm4(al[mt], o + SIM_TILEB);
            }
#pragma unroll
            for (int g = 0; g < 2; ++g) {
                const unsigned o = base + 2 * SIM_TILEB +
                                   (wm + g * 16 + nB) * 80 + (kB + s16 * 16) * 2;
                ldsm4(bh[g], o);
                ldsm4(bl[g], o + SIM_TILEB);
            }
#pragma unroll
            for (int mt = 0; mt < 4; ++mt)
#pragma unroll
                for (int nt = 0; nt < 4; ++nt) {
                    const int g = nt >> 1, q = (nt & 1) * 2;
                    mma16816(acc[mt][nt], ah[mt], bh[g][q], bh[g][q + 1]);
                    mma16816(acc[mt][nt], ah[mt], bl[g][q], bl[g][q + 1]);
                    mma16816(acc[mt][nt], al[mt], bh[g][q], bh[g][q + 1]);
                }
        }
        __syncthreads();
    }

    const float sc = w[0] * (1.f / (float)T_);
    float* C = g_sim + (size_t)b * SL_ * L_ + (size_t)s * L_ * L_;
    const int gg = lane >> 2, tg = (lane & 3) * 2;
#pragma unroll
    for (int mt = 0; mt < 4; ++mt)
#pragma unroll
        for (int nt = 0; nt < 4; ++nt) {
            const int l = l0 + wl + mt * 16 + gg;
            const int m = m0 + wm + nt * 8 + tg;
            const float* a = acc[mt][nt];
            if (l < L_) {
                if (m < L_)     C[(size_t)l * L_ + m]     = a[0] * sc;
                if (m + 1 < L_) C[(size_t)l * L_ + m + 1] = a[1] * sc;
            }
            if (l + 8 < L_) {
                if (m < L_)     C[(size_t)(l + 8) * L_ + m]     = a[2] * sc;
                if (m + 1 < L_) C[(size_t)(l + 8) * L_ + m + 1] = a[3] * sc;
            }
        }
}

// ---------------------------------------------------------------------------
// Kernel 2: softmax over j = s*L+l (stride L_) per (b,m). In place on g_sim.
// ---------------------------------------------------------------------------
__global__ __launch_bounds__(256) void softmax_cols() {
    const int bm = blockIdx.x;
    const int b = bm / L_;
    const int m = bm % L_;
    float* base = g_sim + (size_t)b * SL_ * L_ + m;

    __shared__ float red[256];
    const int tid = threadIdx.x;

    float mx = -1e30f;
    for (int j = tid; j < SL_; j += 256) mx = fmaxf(mx, base[(size_t)j * L_]);
    red[tid] = mx;
    __syncthreads();
    for (int o = 128; o > 0; o >>= 1) {
        if (tid < o) red[tid] = fmaxf(red[tid], red[tid + o]);
        __syncthreads();
    }
    mx = red[0];
    __syncthreads();

    float sum = 0.f;
    for (int j = tid; j < SL_; j += 256) {
        float e = __expf(base[(size_t)j * L_] - mx);
        base[(size_t)j * L_] = e;
        sum += e;
    }
    red[tid] = sum;
    __syncthreads();
    for (int o = 128; o > 0; o >>= 1) {
        if (tid < o) red[tid] += red[tid + o];
        __syncthreads();
    }
    const float inv = 1.f / red[0];
    for (int j = tid; j < SL_; j += 256) base[(size_t)j * L_] *= inv;
}

// ---------------------------------------------------------------------------
// Kernel 3: repack attn view into padded buffer: g_attn[b][l][j], stride 4352.
// attn[b,l,j] = flat g_sim[b][l*SL + j] (the reshape is a contiguous view).
// ---------------------------------------------------------------------------
__global__ __launch_bounds__(256) void repack_attn() {
    const size_t idx = (size_t)blockIdx.x * 256 + threadIdx.x;   // over B*L*SLP
    const size_t per = (size_t)L_ * SLP_;
    const int b = (int)(idx / per);
    const size_t rem = idx - (size_t)b * per;
    const int l = (int)(rem / SLP_);
    const int j = (int)(rem - (size_t)l * SLP_);
    float v = 0.f;
    if (j < SL_) v = g_sim[(size_t)b * SL_ * L_ + (size_t)l * SL_ + j];
    g_attn[idx] = v;
}

// ---------------------------------------------------------------------------
// Kernel 4: out GEMM. out[b,t,l,d] = sum_j attn[b,l,j] * XF[b,t,j,d]
// Block tile 128(l) x 64(d), K = 4352 (padded; pad rows zero), KC=32.
// 8 warps (warp tile 32x32). B operand row-major [j][d] -> ldmatrix .trans.
// ---------------------------------------------------------------------------
#define OUT_ATILE 10240                  // 128 x 80B
#define OUT_BTILE 4608                   // 32 x 144B (64 bf16 + pad 8)
#define OUT_STAGE (2 * OUT_ATILE + 2 * OUT_BTILE)
#define OUT_SMEM  (2 * OUT_STAGE)

__global__ __launch_bounds__(256, 1) void out_gemm(const float* __restrict__ x,
                                                   float* __restrict__ out) {
    extern __shared__ char sm[];
    const int z = blockIdx.z;
    const int b = z / T_, t = z % T_;
    const int l0 = blockIdx.x * 128;
    const int tid = threadIdx.x, lane = tid & 31, wid = tid >> 5;
    const int wl = (wid & 3) * 32, wd = (wid >> 2) * 32;

    const float* attb = g_attn + (size_t)b * L_ * SLP_;
    const float* xb = x + (size_t)b * T_ * L_ * D_;

    const int rA = lane & 15, cA = lane >> 4;
    const int kBt = (lane & 7) + (((lane >> 3) & 1) << 3);   // trans: k row
    const int nBt = (lane >> 4) << 3;                        // trans: n offset

    int rowi[4], c4i[4];
#pragma unroll
    for (int i = 0; i < 4; i++) { int e = tid + i * 256; rowi[i] = e >> 3; c4i[i] = e & 7; }
    const int jB[2] = { tid >> 4, 16 + (tid >> 4) };
    const int d4B = tid & 15;

    float4 stA[4], stB[2];
    auto LDG = [&](int kc) {
        const int j0 = kc * 32;
#pragma unroll
        for (int i = 0; i < 4; i++) {
            const int row = rowi[i], k4 = c4i[i] * 4;
            stA[i] = make_float4(0.f, 0.f, 0.f, 0.f);
            if (l0 + row < L_)
                stA[i] = *(const float4*)(attb + (size_t)(l0 + row) * SLP_ + j0 + k4);
        }
#pragma unroll
        for (int i = 0; i < 2; i++) {
            stB[i] = make_float4(0.f, 0.f, 0.f, 0.f);
            const int jj = j0 + jB[i];
            if (jj < SL_) {
                const int ss = jj / L_;
                const int lk = jj - ss * L_;
                const int tp = t + shift_p(ss);
                if (tp < T_)
                    stB[i] = *(const float4*)(xb + ((size_t)tp * L_ + lk) * D_ + d4B * 4);
            }
        }
    };
    auto STS = [&](int buf) {
        char* base = sm + buf * OUT_STAGE;
#pragma unroll
        for (int i = 0; i < 4; i++) {
            const int off = rowi[i] * 80 + c4i[i] * 8;
            cvt_hl(base + off, base + OUT_ATILE + off, stA[i]);
        }
        char* bb = base + 2 * OUT_ATILE;
#pragma unroll
        for (int i = 0; i < 2; i++) {
            const int off = jB[i] * 144 + d4B * 8;
            cvt_hl(bb + off, bb + OUT_BTILE + off, stB[i]);
        }
    };

    float acc[2][4][4] = {};
    const int nc = SLP_ / 32;   // 136

    LDG(0); STS(0); LDG(1);
    __syncthreads();

    for (int kc = 0; kc < nc; ++kc) {
        const int cur = kc & 1;
        if (kc + 1 < nc) STS(cur ^ 1);
        if (kc + 2 < nc) LDG(kc + 2);
        const unsigned base = sptr(sm + cur * OUT_STAGE);
#pragma unroll
        for (int s16 = 0; s16 < 2; ++s16) {
            unsigned ah[2][4], al[2][4], bh[2][4], bl[2][4];
#pragma unroll
            for (int mt = 0; mt < 2; ++mt) {
                const unsigned o = base + (wl + mt * 16 + rA) * 80 + (s16 * 16 + cA * 8) * 2;
                ldsm4(ah[mt], o);
                ldsm4(al[mt], o + OUT_ATILE);
            }
#pragma unroll
            for (int g = 0; g < 2; ++g) {
                const unsigned o = base + 2 * OUT_ATILE +
                                   (kBt + s16 * 16) * 144 + (wd + g * 16 + nBt) * 2;
                ldsm4t(bh[g], o);
                ldsm4t(bl[g], o + OUT_BTILE);
            }
#pragma unroll
            for (int mt = 0; mt < 2; ++mt)
#pragma unroll
                for (int nt = 0; nt < 4; ++nt) {
                    const int g = nt >> 1, q = (nt & 1) * 2;
                    mma16816(acc[mt][nt], ah[mt], bh[g][q], bh[g][q + 1]);
                    mma16816(acc[mt][nt], ah[mt], bl[g][q], bl[g][q + 1]);
                    mma16816(acc[mt][nt], al[mt], bh[g][q], bh[g][q + 1]);
                }
        }
        __syncthreads();
    }

    float* ob = out + (size_t)(b * T_ + t) * L_ * D_;
    const int gg = lane >> 2, tg = (lane & 3) * 2;
#pragma unroll
    for (int mt = 0; mt < 2; ++mt)
#pragma unroll
        for (int nt = 0; nt < 4; ++nt) {
            const int l = l0 + wl + mt * 16 + gg;
            const int d = wd + nt * 8 + tg;
            const float* a = acc[mt][nt];
            if (l < L_) {
                ob[(size_t)l * D_ + d]     = a[0];
                ob[(size_t)l * D_ + d + 1] = a[1];
            }
            if (l + 8 < L_) {
                ob[(size_t)(l + 8) * D_ + d]     = a[2];
                ob[(size_t)(l + 8) * D_ + d + 1] = a[3];
            }
        }
}

// ---------------------------------------------------------------------------
extern "C" void kernel_launch(void* const* d_in, const int* in_sizes, int n_in,
                              void* d_out, int out_size) {
    const float* x = (const float*)d_in[0];
    const float* w = (const float*)d_in[1];
    float* out = (float*)d_out;

    cudaFuncSetAttribute(sim_gemm, cudaFuncAttributeMaxDynamicSharedMemorySize, SIM_SMEM);
    cudaFuncSetAttribute(out_gemm, cudaFuncAttributeMaxDynamicSharedMemorySize, OUT_SMEM);

    sim_gemm<<<dim3(2, 2, B_ * S_), 256, SIM_SMEM>>>(x, w);
    softmax_cols<<<B_ * L_, 256>>>();
    repack_attn<<<(unsigned)((size_t)B_ * L_ * SLP_ / 256), 256>>>();
    out_gemm<<<dim3(2, 1, B_ * T_), 256, OUT_SMEM>>>(x, out);
}

// round 5
// speedup vs baseline: 3.2350x; 1.3344x over previous
#include <cuda_runtime.h>
#include <cuda_bf16.h>

// Problem constants
#define B_ 2
#define T_ 320
#define L_ 207
#define D_ 64
#define S_ 21
#define SL_ 4347
#define SLP_ 4352       // padded attn row stride

#define XN_ ((size_t)B_ * T_ * L_ * D_)   // 8478720

// Scratch (static device globals; no allocation)
__device__ float g_sim[(size_t)B_ * SL_ * L_];                 // [b][s*L+l][m]
__device__ __align__(16) __nv_bfloat16 g_xh[XN_];              // x hi
__device__ __align__(16) __nv_bfloat16 g_xl[XN_];              // x lo
__device__ __align__(16) __nv_bfloat16 g_ah[(size_t)B_ * L_ * SLP_];  // attn hi
__device__ __align__(16) __nv_bfloat16 g_al[(size_t)B_ * L_ * SLP_];  // attn lo

__device__ __forceinline__ int shift_p(int s) { return (s == 0) ? 287 : (21 - s); }

// ---------------- low-level helpers ----------------
__device__ __forceinline__ unsigned sptr(const void* p) {
    unsigned r;
    asm("{.reg .u64 t; cvta.to.shared.u64 t, %1; cvt.u32.u64 %0, t;}" : "=r"(r) : "l"(p));
    return r;
}
__device__ __forceinline__ void ldsm4(unsigned r[4], unsigned a) {
    asm volatile("ldmatrix.sync.aligned.m8n8.x4.shared.b16 {%0,%1,%2,%3},[%4];"
                 : "=r"(r[0]), "=r"(r[1]), "=r"(r[2]), "=r"(r[3]) : "r"(a));
}
__device__ __forceinline__ void ldsm4t(unsigned r[4], unsigned a) {
    asm volatile("ldmatrix.sync.aligned.m8n8.x4.trans.shared.b16 {%0,%1,%2,%3},[%4];"
                 : "=r"(r[0]), "=r"(r[1]), "=r"(r[2]), "=r"(r[3]) : "r"(a));
}
__device__ __forceinline__ void mma16816(float c[4], const unsigned a[4],
                                         unsigned b0, unsigned b1) {
    asm volatile("mma.sync.aligned.m16n8k16.row.col.f32.bf16.bf16.f32 "
                 "{%0,%1,%2,%3},{%4,%5,%6,%7},{%8,%9},{%0,%1,%2,%3};"
                 : "+f"(c[0]), "+f"(c[1]), "+f"(c[2]), "+f"(c[3])
                 : "r"(a[0]), "r"(a[1]), "r"(a[2]), "r"(a[3]), "r"(b0), "r"(b1));
}
__device__ __forceinline__ void cpa(unsigned dst, const void* src, bool v) {
    int sz = v ? 16 : 0;
    asm volatile("cp.async.cg.shared.global [%0], [%1], 16, %2;"
                 :: "r"(dst), "l"(src), "r"(sz));
}
#define CP_COMMIT() asm volatile("cp.async.commit_group;")
#define CP_WAIT1()  asm volatile("cp.async.wait_group 1;")

// fp32x4 -> hi/lo bf16x4 (generic pointer, works for global)
__device__ __forceinline__ void cvt4(float4 v, __nv_bfloat16* hp, __nv_bfloat16* lp) {
    __nv_bfloat16 h0 = __float2bfloat16(v.x), h1 = __float2bfloat16(v.y);
    __nv_bfloat16 h2 = __float2bfloat16(v.z), h3 = __float2bfloat16(v.w);
    *(__nv_bfloat162*)(hp)     = __halves2bfloat162(h0, h1);
    *(__nv_bfloat162*)(hp + 2) = __halves2bfloat162(h2, h3);
    *(__nv_bfloat162*)(lp)     = __halves2bfloat162(__float2bfloat16(v.x - __bfloat162float(h0)),
                                                    __float2bfloat16(v.y - __bfloat162float(h1)));
    *(__nv_bfloat162*)(lp + 2) = __halves2bfloat162(__float2bfloat16(v.z - __bfloat162float(h2)),
                                                    __float2bfloat16(v.w - __bfloat162float(h3)));
}

// ---------------------------------------------------------------------------
// Kernel 0: x fp32 -> bf16 hi/lo
// ---------------------------------------------------------------------------
__global__ __launch_bounds__(256) void cvt_x(const float* __restrict__ x) {
    const size_t idx = ((size_t)blockIdx.x * 256 + threadIdx.x) * 4;
    if (idx >= XN_) return;
    cvt4(*(const float4*)(x + idx), g_xh + idx, g_xl + idx);
}

// ---------------------------------------------------------------------------
// Kernel 1: sim GEMM. C[l,m] = (w/T) * sum_{t,d} x[t,l,d]*x[t+p,m,d]
// Block 128(l) x 64(m), KC=32, 8 warps (32x32 each), bf16 3-pass MMA,
// cp.async double-buffered.
// ---------------------------------------------------------------------------
#define SIM_A 10240                    // 128 rows * 80B
#define SIM_B 5120                     // 64 rows * 80B
#define SIM_STAGE (2 * SIM_A + 2 * SIM_B)   // 30720
#define SIM_SMEM  (2 * SIM_STAGE)

__global__ __launch_bounds__(256, 2) void sim_gemm(const float* __restrict__ w) {
    extern __shared__ char sm[];
    const int z = blockIdx.z;
    const int b = z & 1;
    const int s = ((z >> 1) + 1) % S_;      // s=0 (tiny K) last
    const int p = shift_p(s);
    const int Tv = T_ - p;
    const int l0 = blockIdx.x * 128, m0 = blockIdx.y * 64;
    const int tid = threadIdx.x, lane = tid & 31, wid = tid >> 5;
    const int wl = (wid & 3) * 32, wm = (wid >> 2) * 32;

    const size_t xoff = (size_t)b * T_ * L_ * D_;
    const __nv_bfloat16* xh = g_xh + xoff;
    const __nv_bfloat16* xl = g_xl + xoff;

    // ldmatrix lane addressing (as validated in R3)
    const int rA = lane & 15, cA = lane >> 4;
    const int nB = ((lane >> 4) << 3) + (lane & 7);
    const int kB = ((lane >> 3) & 1) << 3;

    // loader mapping
    const int arow = tid >> 1, ahalf = tid & 1;        // A: 2 thr/row, 32B each
    const int brow = tid >> 2, bq = tid & 3;           // B: 4 thr/row, 16B each
    const bool av = (l0 + arow) < L_;
    const bool bv = (m0 + brow) < L_;

    auto ISSUE = [&](int kc, int buf) {
        const int t = kc >> 1, db = (kc & 1) * 32;
        const unsigned sb = sptr(sm + buf * SIM_STAGE);
        // A (Ah, Al): rows l0+arow, 32 bf16
        const size_t ao = ((size_t)t * L_ + l0 + arow) * D_ + db + ahalf * 16;
        const unsigned ad = sb + arow * 80 + ahalf * 32;
        cpa(ad,              xh + ao,     av);
        cpa(ad + 16,         xh + ao + 8, av);
        cpa(ad + SIM_A,      xl + ao,     av);
        cpa(ad + SIM_A + 16, xl + ao + 8, av);
        // B (Bh, Bl): rows m0+brow at t+p
        const size_t bo = ((size_t)(t + p) * L_ + m0 + brow) * D_ + db + bq * 8;
        const unsigned bd = sb + 2 * SIM_A + brow * 80 + bq * 16;
        cpa(bd,         xh + bo, bv);
        cpa(bd + SIM_B, xl + bo, bv);
    };

    float acc[2][4][4] = {};
    const int nc = Tv * 2;

    ISSUE(0, 0); CP_COMMIT();
    ISSUE(1, 1); CP_COMMIT();
    CP_WAIT1();
    __syncthreads();

    for (int kc = 0; kc < nc; ++kc) {
        const int cur = kc & 1;
        const unsigned base = sptr(sm + cur * SIM_STAGE);
#pragma unroll
        for (int s16 = 0; s16 < 2; ++s16) {
            unsigned ah[2][4], al[2][4], bh[2][4], bl[2][4];
#pragma unroll
            for (int mt = 0; mt < 2; ++mt) {
                const unsigned o = base + (wl + mt * 16 + rA) * 80 + (s16 * 16 + cA * 8) * 2;
                ldsm4(ah[mt], o);
                ldsm4(al[mt], o + SIM_A);
            }
#pragma unroll
            for (int g = 0; g < 2; ++g) {
                const unsigned o = base + 2 * SIM_A + (wm + g * 16 + nB) * 80 + (kB + s16 * 16) * 2;
                ldsm4(bh[g], o);
                ldsm4(bl[g], o + SIM_B);
            }
#pragma unroll
            for (int mt = 0; mt < 2; ++mt)
#pragma unroll
                for (int nt = 0; nt < 4; ++nt) {
                    const int g = nt >> 1, q = (nt & 1) * 2;
                    mma16816(acc[mt][nt], ah[mt], bh[g][q], bh[g][q + 1]);
                    mma16816(acc[mt][nt], ah[mt], bl[g][q], bl[g][q + 1]);
                    mma16816(acc[mt][nt], al[mt], bh[g][q], bh[g][q + 1]);
                }
        }
        __syncthreads();
        if (kc + 2 < nc) { ISSUE(kc + 2, cur); CP_COMMIT(); }
        if (kc + 1 < nc) { CP_WAIT1(); __syncthreads(); }
    }

    const float sc = w[0] * (1.f / (float)T_);
    float* C = g_sim + (size_t)b * SL_ * L_ + (size_t)s * L_ * L_;
    const int gg = lane >> 2, tg = (lane & 3) * 2;
#pragma unroll
    for (int mt = 0; mt < 2; ++mt)
#pragma unroll
        for (int nt = 0; nt < 4; ++nt) {
            const int l = l0 + wl + mt * 16 + gg;
            const int m = m0 + wm + nt * 8 + tg;
            const float* a = acc[mt][nt];
            if (l < L_) {
                if (m < L_)     C[(size_t)l * L_ + m]     = a[0] * sc;
                if (m + 1 < L_) C[(size_t)l * L_ + m + 1] = a[1] * sc;
            }
            if (l + 8 < L_) {
                if (m < L_)     C[(size_t)(l + 8) * L_ + m]     = a[2] * sc;
                if (m + 1 < L_) C[(size_t)(l + 8) * L_ + m + 1] = a[3] * sc;
            }
        }
}

// ---------------------------------------------------------------------------
// Kernel 2: softmax over j = s*L+l (stride L_) per (b,m). In place on g_sim.
// ---------------------------------------------------------------------------
__global__ __launch_bounds__(256) void softmax_cols() {
    const int bm = blockIdx.x;
    const int b = bm / L_;
    const int m = bm % L_;
    float* base = g_sim + (size_t)b * SL_ * L_ + m;

    __shared__ float red[256];
    const int tid = threadIdx.x;

    float mx = -1e30f;
    for (int j = tid; j < SL_; j += 256) mx = fmaxf(mx, base[(size_t)j * L_]);
    red[tid] = mx;
    __syncthreads();
    for (int o = 128; o > 0; o >>= 1) {
        if (tid < o) red[tid] = fmaxf(red[tid], red[tid + o]);
        __syncthreads();
    }
    mx = red[0];
    __syncthreads();

    float sum = 0.f;
    for (int j = tid; j < SL_; j += 256) {
        float e = __expf(base[(size_t)j * L_] - mx);
        base[(size_t)j * L_] = e;
        sum += e;
    }
    red[tid] = sum;
    __syncthreads();
    for (int o = 128; o > 0; o >>= 1) {
        if (tid < o) red[tid] += red[tid + o];
        __syncthreads();
    }
    const float inv = 1.f / red[0];
    for (int j = tid; j < SL_; j += 256) base[(size_t)j * L_] *= inv;
}

// ---------------------------------------------------------------------------
// Kernel 3: repack attn view -> padded bf16 hi/lo: g_ah/g_al[b][l][j].
// attn[b,l,j] = flat g_sim[b][l*SL + j] (the reshape is a contiguous view).
// ---------------------------------------------------------------------------
__global__ __launch_bounds__(256) void repack_attn() {
    const size_t i4 = (size_t)blockIdx.x * 256 + threadIdx.x;
    const size_t idx = i4 * 4;
    if (idx >= (size_t)B_ * L_ * SLP_) return;
    const size_t per = (size_t)L_ * SLP_;
    const int b = (int)(idx / per);
    const size_t rem = idx - (size_t)b * per;
    const int l = (int)(rem / SLP_);
    const int j = (int)(rem - (size_t)l * SLP_);
    const float* src = g_sim + (size_t)b * SL_ * L_ + (size_t)l * SL_ + j;
    float4 v;
    v.x = (j     < SL_) ? src[0] : 0.f;
    v.y = (j + 1 < SL_) ? src[1] : 0.f;
    v.z = (j + 2 < SL_) ? src[2] : 0.f;
    v.w = (j + 3 < SL_) ? src[3] : 0.f;
    cvt4(v, g_ah + idx, g_al + idx);
}

// ---------------------------------------------------------------------------
// Kernel 4: out GEMM. out[b,t,l,d] = sum_j attn[b,l,j] * XF[b,t,j,d]
// Block 128(l) x 64(d) per (b,t), K=4352 (pad zero), KC=32, 8 warps (32x32).
// ---------------------------------------------------------------------------
#define OUT_A 10240                     // 128 x 80B
#define OUT_B 4608                      // 32 x 144B
#define OUT_STAGE (2 * OUT_A + 2 * OUT_B)   // 29696
#define OUT_SMEM  (2 * OUT_STAGE)

__global__ __launch_bounds__(256, 2) void out_gemm(float* __restrict__ out) {
    extern __shared__ char sm[];
    const int z = blockIdx.z;
    const int b = z / T_, t = z % T_;
    const int l0 = blockIdx.x * 128;
    const int tid = threadIdx.x, lane = tid & 31, wid = tid >> 5;
    const int wl = (wid & 3) * 32, wd = (wid >> 2) * 32;

    const __nv_bfloat16* ah_g = g_ah + (size_t)b * L_ * SLP_;
    const __nv_bfloat16* al_g = g_al + (size_t)b * L_ * SLP_;
    const size_t xoff = (size_t)b * T_ * L_ * D_;
    const __nv_bfloat16* xh = g_xh + xoff;
    const __nv_bfloat16* xl = g_xl + xoff;

    const int rA = lane & 15, cA = lane >> 4;
    const int kBt = (lane & 7) + (((lane >> 3) & 1) << 3);
    const int nBt = (lane >> 4) << 3;

    const int arow = tid >> 1, ahalf = tid & 1;   // A: 128 rows, 2 thr/row
    const int brow = tid >> 3, bseg = tid & 7;    // B: 32 rows, 8 thr/row
    const bool av = (l0 + arow) < L_;

    auto ISSUE = [&](int kc, int buf) {
        const int j0 = kc * 32;
        const unsigned sb = sptr(sm + buf * OUT_STAGE);
        // A (attn hi/lo)
        const size_t ao = (size_t)(l0 + arow) * SLP_ + j0 + ahalf * 16;
        const unsigned ad = sb + arow * 80 + ahalf * 32;
        cpa(ad,              ah_g + ao,     av);
        cpa(ad + 16,         ah_g + ao + 8, av);
        cpa(ad + OUT_A,      al_g + ao,     av);
        cpa(ad + OUT_A + 16, al_g + ao + 8, av);
        // B (gathered shifted x): row j0+brow, 64 bf16
        const int j = j0 + brow;
        int ss = j / L_;
        int lk = j - ss * L_;
        int tp = t + shift_p(ss);
        const bool bvv = (j < SL_) && (tp < T_);
        const size_t bo = ((size_t)tp * L_ + lk) * D_ + bseg * 8;
        const unsigned bd = sb + 2 * OUT_A + brow * 144 + bseg * 16;
        cpa(bd,         xh + bo, bvv);
        cpa(bd + OUT_B, xl + bo, bvv);
    };

    float acc[2][4][4] = {};
    const int nc = SLP_ / 32;   // 136

    ISSUE(0, 0); CP_COMMIT();
    ISSUE(1, 1); CP_COMMIT();
    CP_WAIT1();
    __syncthreads();

    for (int kc = 0; kc < nc; ++kc) {
        const int cur = kc & 1;
        const unsigned base = sptr(sm + cur * OUT_STAGE);
#pragma unroll
        for (int s16 = 0; s16 < 2; ++s16) {
            unsigned ah[2][4], al[2][4], bh[2][4], bl[2][4];
#pragma unroll
            for (int mt = 0; mt < 2; ++mt) {
                const unsigned o = base + (wl + mt * 16 + rA) * 80 + (s16 * 16 + cA * 8) * 2;
                ldsm4(ah[mt], o);
                ldsm4(al[mt], o + OUT_A);
            }
#pragma unroll
            for (int g = 0; g < 2; ++g) {
                const unsigned o = base + 2 * OUT_A +
                                   (kBt + s16 * 16) * 144 + (wd + g * 16 + nBt) * 2;
                ldsm4t(bh[g], o);
                ldsm4t(bl[g], o + OUT_B);
            }
#pragma unroll
            for (int mt = 0; mt < 2; ++mt)
#pragma unroll
                for (int nt = 0; nt < 4; ++nt) {
                    const int g = nt >> 1, q = (nt & 1) * 2;
                    mma16816(acc[mt][nt], ah[mt], bh[g][q], bh[g][q + 1]);
                    mma16816(acc[mt][nt], ah[mt], bl[g][q], bl[g][q + 1]);
                    mma16816(acc[mt][nt], al[mt], bh[g][q], bh[g][q + 1]);
                }
        }
        __syncthreads();
        if (kc + 2 < nc) { ISSUE(kc + 2, cur); CP_COMMIT(); }
        if (kc + 1 < nc) { CP_WAIT1(); __syncthreads(); }
    }

    float* ob = out + (size_t)(b * T_ + t) * L_ * D_;
    const int gg = lane >> 2, tg = (lane & 3) * 2;
#pragma unroll
    for (int mt = 0; mt < 2; ++mt)
#pragma unroll
        for (int nt = 0; nt < 4; ++nt) {
            const int l = l0 + wl + mt * 16 + gg;
            const int d = wd + nt * 8 + tg;
            const float* a = acc[mt][nt];
            if (l < L_) {
                ob[(size_t)l * D_ + d]     = a[0];
                ob[(size_t)l * D_ + d + 1] = a[1];
            }
            if (l + 8 < L_) {
                ob[(size_t)(l + 8) * D_ + d]     = a[2];
                ob[(size_t)(l + 8) * D_ + d + 1] = a[3];
            }
        }
}

// ---------------------------------------------------------------------------
extern "C" void kernel_launch(void* const* d_in, const int* in_sizes, int n_in,
                              void* d_out, int out_size) {
    const float* x = (const float*)d_in[0];
    const float* w = (const float*)d_in[1];
    float* out = (float*)d_out;

    cudaFuncSetAttribute(sim_gemm, cudaFuncAttributeMaxDynamicSharedMemorySize, SIM_SMEM);
    cudaFuncSetAttribute(out_gemm, cudaFuncAttributeMaxDynamicSharedMemorySize, OUT_SMEM);

    cvt_x<<<(unsigned)((XN_ / 4 + 255) / 256), 256>>>(x);
    sim_gemm<<<dim3(2, 4, B_ * S_), 256, SIM_SMEM>>>(w);
    softmax_cols<<<B_ * L_, 256>>>();
    repack_attn<<<(unsigned)(((size_t)B_ * L_ * SLP_ / 4 + 255) / 256), 256>>>();
    out_gemm<<<dim3(2, 1, B_ * T_), 256, OUT_SMEM>>>(out);
}

// round 7
// speedup vs baseline: 3.6008x; 1.1131x over previous
#include <cuda_runtime.h>
#include <cuda_bf16.h>

// Problem constants
#define B_ 2
#define T_ 320
#define L_ 207
#define D_ 64
#define S_ 21
#define SL_ 4347
#define SLP_ 4352       // padded attn row stride

#define XN_ ((size_t)B_ * T_ * L_ * D_)   // 8478720

// Scratch (static device globals; no allocation)
__device__ float g_sim[(size_t)B_ * SL_ * L_];                 // [b][s*L+l][m]
__device__ __align__(16) __nv_bfloat16 g_xh[XN_];              // x hi
__device__ __align__(16) __nv_bfloat16 g_xl[XN_];              // x lo
__device__ __align__(16) __nv_bfloat16 g_ah[(size_t)B_ * L_ * SLP_];  // attn hi
__device__ __align__(16) __nv_bfloat16 g_al[(size_t)B_ * L_ * SLP_];  // attn lo

__device__ __forceinline__ int shift_p(int s) { return (s == 0) ? 287 : (21 - s); }

// ---------------- low-level helpers ----------------
__device__ __forceinline__ unsigned sptr(const void* p) {
    unsigned r;
    asm("{.reg .u64 t; cvta.to.shared.u64 t, %1; cvt.u32.u64 %0, t;}" : "=r"(r) : "l"(p));
    return r;
}
__device__ __forceinline__ void ldsm4(unsigned r[4], unsigned a) {
    asm volatile("ldmatrix.sync.aligned.m8n8.x4.shared.b16 {%0,%1,%2,%3},[%4];"
                 : "=r"(r[0]), "=r"(r[1]), "=r"(r[2]), "=r"(r[3]) : "r"(a));
}
__device__ __forceinline__ void ldsm4t(unsigned r[4], unsigned a) {
    asm volatile("ldmatrix.sync.aligned.m8n8.x4.trans.shared.b16 {%0,%1,%2,%3},[%4];"
                 : "=r"(r[0]), "=r"(r[1]), "=r"(r[2]), "=r"(r[3]) : "r"(a));
}
__device__ __forceinline__ void mma16816(float c[4], const unsigned a[4],
                                         unsigned b0, unsigned b1) {
    asm volatile("mma.sync.aligned.m16n8k16.row.col.f32.bf16.bf16.f32 "
                 "{%0,%1,%2,%3},{%4,%5,%6,%7},{%8,%9},{%0,%1,%2,%3};"
                 : "+f"(c[0]), "+f"(c[1]), "+f"(c[2]), "+f"(c[3])
                 : "r"(a[0]), "r"(a[1]), "r"(a[2]), "r"(a[3]), "r"(b0), "r"(b1));
}
__device__ __forceinline__ void cpa(unsigned dst, const void* src, bool v) {
    int sz = v ? 16 : 0;
    asm volatile("cp.async.cg.shared.global [%0], [%1], 16, %2;"
                 :: "r"(dst), "l"(src), "r"(sz));
}
#define CP_COMMIT() asm volatile("cp.async.commit_group;")
#define CP_WAIT1()  asm volatile("cp.async.wait_group 1;")
#define CP_WAIT0()  asm volatile("cp.async.wait_group 0;")

// fp32x4 -> hi/lo bf16x4
__device__ __forceinline__ void cvt4(float4 v, __nv_bfloat16* hp, __nv_bfloat16* lp) {
    __nv_bfloat16 h0 = __float2bfloat16(v.x), h1 = __float2bfloat16(v.y);
    __nv_bfloat16 h2 = __float2bfloat16(v.z), h3 = __float2bfloat16(v.w);
    *(__nv_bfloat162*)(hp)     = __halves2bfloat162(h0, h1);
    *(__nv_bfloat162*)(hp + 2) = __halves2bfloat162(h2, h3);
    *(__nv_bfloat162*)(lp)     = __halves2bfloat162(__float2bfloat16(v.x - __bfloat162float(h0)),
                                                    __float2bfloat16(v.y - __bfloat162float(h1)));
    *(__nv_bfloat162*)(lp + 2) = __halves2bfloat162(__float2bfloat16(v.z - __bfloat162float(h2)),
                                                    __float2bfloat16(v.w - __bfloat162float(h3)));
}

// ---------------------------------------------------------------------------
// Kernel 0: x fp32 -> bf16 hi/lo
// ---------------------------------------------------------------------------
__global__ __launch_bounds__(256) void cvt_x(const float* __restrict__ x) {
    const size_t idx = ((size_t)blockIdx.x * 256 + threadIdx.x) * 4;
    if (idx >= XN_) return;
    cvt4(*(const float4*)(x + idx), g_xh + idx, g_xl + idx);
}

// ---------------------------------------------------------------------------
// Kernel 1: sim GEMM. C[l,m] = (w/T) * sum_{t,d} x[t,l,d]*x[t+p,m,d]
// Block 128(l) x 64(m), KC=32, 8 warps (32x32 each), bf16 3-pass MMA,
// 3-stage cp.async ring with a single barrier per chunk.
// ---------------------------------------------------------------------------
#define SIM_A 10240                    // 128 rows * 80B
#define SIM_B 5120                     // 64 rows * 80B
#define SIM_STAGE (2 * SIM_A + 2 * SIM_B)   // 30720
#define SIM_SMEM  (3 * SIM_STAGE)           // 92160

__global__ __launch_bounds__(256, 2) void sim_gemm(const float* __restrict__ w) {
    extern __shared__ char sm[];
    const int z = blockIdx.z;
    const int b = z & 1;
    const int s = ((z >> 1) + 1) % S_;      // s=0 (tiny K) last
    const int p = shift_p(s);
    const int Tv = T_ - p;
    const int l0 = blockIdx.x * 128, m0 = blockIdx.y * 64;
    const int tid = threadIdx.x, lane = tid & 31, wid = tid >> 5;
    const int wl = (wid & 3) * 32, wm = (wid >> 2) * 32;

    const size_t xoff = (size_t)b * T_ * L_ * D_;
    const __nv_bfloat16* xh = g_xh + xoff;
    const __nv_bfloat16* xl = g_xl + xoff;

    const int rA = lane & 15, cA = lane >> 4;
    const int nB = ((lane >> 4) << 3) + (lane & 7);
    const int kB = ((lane >> 3) & 1) << 3;

    const int arow = tid >> 1, ahalf = tid & 1;
    const int brow = tid >> 2, bq = tid & 3;
    const bool av = (l0 + arow) < L_;
    const bool bv = (m0 + brow) < L_;

    auto ISSUE = [&](int kc, int buf) {
        const int t = kc >> 1, db = (kc & 1) * 32;
        const unsigned sb = sptr(sm + buf * SIM_STAGE);
        const size_t ao = ((size_t)t * L_ + l0 + arow) * D_ + db + ahalf * 16;
        const unsigned ad = sb + arow * 80 + ahalf * 32;
        cpa(ad,              xh + ao,     av);
        cpa(ad + 16,         xh + ao + 8, av);
        cpa(ad + SIM_A,      xl + ao,     av);
        cpa(ad + SIM_A + 16, xl + ao + 8, av);
        const size_t bo = ((size_t)(t + p) * L_ + m0 + brow) * D_ + db + bq * 8;
        const unsigned bd = sb + 2 * SIM_A + brow * 80 + bq * 16;
        cpa(bd,         xh + bo, bv);
        cpa(bd + SIM_B, xl + bo, bv);
    };

    float acc[2][4][4] = {};
    const int nc = Tv * 2;

    ISSUE(0, 0); CP_COMMIT();
    ISSUE(1, 1); CP_COMMIT();

    for (int kc = 0; kc < nc; ++kc) {
        if (kc + 1 < nc) { CP_WAIT1(); } else { CP_WAIT0(); }
        __syncthreads();
        const unsigned base = sptr(sm + (kc % 3) * SIM_STAGE);
#pragma unroll
        for (int s16 = 0; s16 < 2; ++s16) {
            unsigned ah[2][4], al[2][4], bh[2][4], bl[2][4];
#pragma unroll
            for (int mt = 0; mt < 2; ++mt) {
                const unsigned o = base + (wl + mt * 16 + rA) * 80 + (s16 * 16 + cA * 8) * 2;
                ldsm4(ah[mt], o);
                ldsm4(al[mt], o + SIM_A);
            }
#pragma unroll
            for (int g = 0; g < 2; ++g) {
                const unsigned o = base + 2 * SIM_A + (wm + g * 16 + nB) * 80 + (kB + s16 * 16) * 2;
                ldsm4(bh[g], o);
                ldsm4(bl[g], o + SIM_B);
            }
            // pass-outer ordering: dependent MMAs into one acc are 8 apart
#pragma unroll
            for (int mt = 0; mt < 2; ++mt)
#pragma unroll
                for (int nt = 0; nt < 4; ++nt)
                    mma16816(acc[mt][nt], ah[mt], bh[nt >> 1][(nt & 1) * 2],
                                                  bh[nt >> 1][(nt & 1) * 2 + 1]);
#pragma unroll
            for (int mt = 0; mt < 2; ++mt)
#pragma unroll
                for (int nt = 0; nt < 4; ++nt)
                    mma16816(acc[mt][nt], ah[mt], bl[nt >> 1][(nt & 1) * 2],
                                                  bl[nt >> 1][(nt & 1) * 2 + 1]);
#pragma unroll
            for (int mt = 0; mt < 2; ++mt)
#pragma unroll
                for (int nt = 0; nt < 4; ++nt)
                    mma16816(acc[mt][nt], al[mt], bh[nt >> 1][(nt & 1) * 2],
                                                  bh[nt >> 1][(nt & 1) * 2 + 1]);
        }
        if (kc + 2 < nc) { ISSUE(kc + 2, (kc + 2) % 3); CP_COMMIT(); }
    }

    const float sc = w[0] * (1.f / (float)T_);
    float* C = g_sim + (size_t)b * SL_ * L_ + (size_t)s * L_ * L_;
    const int gg = lane >> 2, tg = (lane & 3) * 2;
#pragma unroll
    for (int mt = 0; mt < 2; ++mt)
#pragma unroll
        for (int nt = 0; nt < 4; ++nt) {
            const int l = l0 + wl + mt * 16 + gg;
            const int m = m0 + wm + nt * 8 + tg;
            const float* a = acc[mt][nt];
            if (l < L_) {
                if (m < L_)     C[(size_t)l * L_ + m]     = a[0] * sc;
                if (m + 1 < L_) C[(size_t)l * L_ + m + 1] = a[1] * sc;
            }
            if (l + 8 < L_) {
                if (m < L_)     C[(size_t)(l + 8) * L_ + m]     = a[2] * sc;
                if (m + 1 < L_) C[(size_t)(l + 8) * L_ + m + 1] = a[3] * sc;
            }
        }
}

// ---------------------------------------------------------------------------
// Kernel 2: softmax over j = s*L+l (stride L_) per (b,m). In place on g_sim.
// ---------------------------------------------------------------------------
__global__ __launch_bounds__(256) void softmax_cols() {
    const int bm = blockIdx.x;
    const int b = bm / L_;
    const int m = bm % L_;
    float* base = g_sim + (size_t)b * SL_ * L_ + m;

    __shared__ float red[256];
    const int tid = threadIdx.x;

    float mx = -1e30f;
    for (int j = tid; j < SL_; j += 256) mx = fmaxf(mx, base[(size_t)j * L_]);
    red[tid] = mx;
    __syncthreads();
    for (int o = 128; o > 0; o >>= 1) {
        if (tid < o) red[tid] = fmaxf(red[tid], red[tid + o]);
        __syncthreads();
    }
    mx = red[0];
    __syncthreads();

    float sum = 0.f;
    for (int j = tid; j < SL_; j += 256) {
        float e = __expf(base[(size_t)j * L_] - mx);
        base[(size_t)j * L_] = e;
        sum += e;
    }
    red[tid] = sum;
    __syncthreads();
    for (int o = 128; o > 0; o >>= 1) {
        if (tid < o) red[tid] += red[tid + o];
        __syncthreads();
    }
    const float inv = 1.f / red[0];
    for (int j = tid; j < SL_; j += 256) base[(size_t)j * L_] *= inv;
}

// ---------------------------------------------------------------------------
// Kernel 3: repack attn view -> padded bf16 hi/lo (g_ah/g_al, stride 4352).
// attn[b,l,j] = flat g_sim[b][l*SL + j] (the reshape is a contiguous view).
// ---------------------------------------------------------------------------
__global__ __launch_bounds__(256) void repack_attn() {
    const size_t idx = ((size_t)blockIdx.x * 256 + threadIdx.x) * 4;
    if (idx >= (size_t)B_ * L_ * SLP_) return;
    const size_t per = (size_t)L_ * SLP_;
    const int b = (int)(idx / per);
    const size_t rem = idx - (size_t)b * per;
    const int l = (int)(rem / SLP_);
    const int j = (int)(rem - (size_t)l * SLP_);
    const float* src = g_sim + (size_t)b * SL_ * L_ + (size_t)l * SL_ + j;
    float4 v;
    v.x = (j     < SL_) ? src[0] : 0.f;
    v.y = (j + 1 < SL_) ? src[1] : 0.f;
    v.z = (j + 2 < SL_) ? src[2] : 0.f;
    v.w = (j + 3 < SL_) ? src[3] : 0.f;
    cvt4(v, g_ah + idx, g_al + idx);
}

// ---------------------------------------------------------------------------
// Kernel 4: out GEMM. out[b,t,l,d] = sum_j attn[b,l,j] * XF[b,t,j,d]
// Block 128(l) x 64(d) per (b,t), K=4352 (pad zero), KC=32, 8 warps (32x32),
// 3-stage ring, single barrier per chunk.
// ---------------------------------------------------------------------------
#define OUT_A 10240                     // 128 x 80B
#define OUT_B 4608                      // 32 x 144B
#define OUT_STAGE (2 * OUT_A + 2 * OUT_B)   // 29696
#define OUT_SMEM  (3 * OUT_STAGE)           // 89088

__global__ __launch_bounds__(256, 2) void out_gemm(float* __restrict__ out) {
    extern __shared__ char sm[];
    const int z = blockIdx.z;
    const int b = z / T_, t = z % T_;
    const int l0 = blockIdx.x * 128;
    const int tid = threadIdx.x, lane = tid & 31, wid = tid >> 5;
    const int wl = (wid & 3) * 32, wd = (wid >> 2) * 32;

    const __nv_bfloat16* ah_g = g_ah + (size_t)b * L_ * SLP_;
    const __nv_bfloat16* al_g = g_al + (size_t)b * L_ * SLP_;
    const size_t xoff = (size_t)b * T_ * L_ * D_;
    const __nv_bfloat16* xh = g_xh + xoff;
    const __nv_bfloat16* xl = g_xl + xoff;

    const int rA = lane & 15, cA = lane >> 4;
    const int kBt = (lane & 7) + (((lane >> 3) & 1) << 3);
    const int nBt = (lane >> 4) << 3;

    const int arow = tid >> 1, ahalf = tid & 1;
    const int brow = tid >> 3, bseg = tid & 7;
    const bool av = (l0 + arow) < L_;

    auto ISSUE = [&](int kc, int buf) {
        const int j0 = kc * 32;
        const unsigned sb = sptr(sm + buf * OUT_STAGE);
        const size_t ao = (size_t)(l0 + arow) * SLP_ + j0 + ahalf * 16;
        const unsigned ad = sb + arow * 80 + ahalf * 32;
        cpa(ad,              ah_g + ao,     av);
        cpa(ad + 16,         ah_g + ao + 8, av);
        cpa(ad + OUT_A,      al_g + ao,     av);
        cpa(ad + OUT_A + 16, al_g + ao + 8, av);
        const int j = j0 + brow;
        int ss = j / L_;
        int lk = j - ss * L_;
        int tp = t + shift_p(ss);
        const bool bvv = (j < SL_) && (tp < T_);
        const size_t bo = ((size_t)tp * L_ + lk) * D_ + bseg * 8;
        const unsigned bd = sb + 2 * OUT_A + brow * 144 + bseg * 16;
        cpa(bd,         xh + bo, bvv);
        cpa(bd + OUT_B, xl + bo, bvv);
    };

    float acc[2][4][4] = {};
    const int nc = SLP_ / 32;   // 136

    ISSUE(0, 0); CP_COMMIT();
    ISSUE(1, 1); CP_COMMIT();

    for (int kc = 0; kc < nc; ++kc) {
        if (kc + 1 < nc) { CP_WAIT1(); } else { CP_WAIT0(); }
        __syncthreads();
        const unsigned base = sptr(sm + (kc % 3) * OUT_STAGE);
#pragma unroll
        for (int s16 = 0; s16 < 2; ++s16) {
            unsigned ah[2][4], al[2][4], bh[2][4], bl[2][4];
#pragma unroll
            for (int mt = 0; mt < 2; ++mt) {
                const unsigned o = base + (wl + mt * 16 + rA) * 80 + (s16 * 16 + cA * 8) * 2;
                ldsm4(ah[mt], o);
                ldsm4(al[mt], o + OUT_A);
            }
#pragma unroll
            for (int g = 0; g < 2; ++g) {
                const unsigned o = base + 2 * OUT_A +
                                   (kBt + s16 * 16) * 144 + (wd + g * 16 + nBt) * 2;
                ldsm4t(bh[g], o);
                ldsm4t(bl[g], o + OUT_B);
            }
#pragma unroll
            for (int mt = 0; mt < 2; ++mt)
#pragma unroll
                for (int nt = 0; nt < 4; ++nt)
                    mma16816(acc[mt][nt], ah[mt], bh[nt >> 1][(nt & 1) * 2],
                                                  bh[nt >> 1][(nt & 1) * 2 + 1]);
#pragma unroll
            for (int mt = 0; mt < 2; ++mt)
#pragma unroll
                for (int nt = 0; nt < 4; ++nt)
                    mma16816(acc[mt][nt], ah[mt], bl[nt >> 1][(nt & 1) * 2],
                                                  bl[nt >> 1][(nt & 1) * 2 + 1]);
#pragma unroll
            for (int mt = 0; mt < 2; ++mt)
#pragma unroll
                for (int nt = 0; nt < 4; ++nt)
                    mma16816(acc[mt][nt], al[mt], bh[nt >> 1][(nt & 1) * 2],
                                                  bh[nt >> 1][(nt & 1) * 2 + 1]);
        }
        if (kc + 2 < nc) { ISSUE(kc + 2, (kc + 2) % 3); CP_COMMIT(); }
    }

    float* ob = out + (size_t)(b * T_ + t) * L_ * D_;
    const int gg = lane >> 2, tg = (lane & 3) * 2;
#pragma unroll
    for (int mt = 0; mt < 2; ++mt)
#pragma unroll
        for (int nt = 0; nt < 4; ++nt) {
            const int l = l0 + wl + mt * 16 + gg;
            const int d = wd + nt * 8 + tg;
            const float* a = acc[mt][nt];
            if (l < L_) {
                ob[(size_t)l * D_ + d]     = a[0];
                ob[(size_t)l * D_ + d + 1] = a[1];
            }
            if (l + 8 < L_) {
                ob[(size_t)(l + 8) * D_ + d]     = a[2];
                ob[(size_t)(l + 8) * D_ + d + 1] = a[3];
            }
        }
}

// ---------------------------------------------------------------------------
extern "C" void kernel_launch(void* const* d_in, const int* in_sizes, int n_in,
                              void* d_out, int out_size) {
    const float* x = (const float*)d_in[0];
    const float* w = (const float*)d_in[1];
    float* out = (float*)d_out;

    cudaFuncSetAttribute(sim_gemm, cudaFuncAttributeMaxDynamicSharedMemorySize, SIM_SMEM);
    cudaFuncSetAttribute(out_gemm, cudaFuncAttributeMaxDynamicSharedMemorySize, OUT_SMEM);

    cvt_x<<<(unsigned)((XN_ / 4 + 255) / 256), 256>>>(x);
    sim_gemm<<<dim3(2, 4, B_ * S_), 256, SIM_SMEM>>>(w);
    softmax_cols<<<B_ * L_, 256>>>();
    repack_attn<<<(unsigned)(((size_t)B_ * L_ * SLP_ / 4 + 255) / 256), 256>>>();
    out_gemm<<<dim3(2, 1, B_ * T_), 256, OUT_SMEM>>>(out);
}